// round 5
// baseline (speedup 1.0000x reference)
#include <cuda_runtime.h>
#include <cstdint>
#include <cstddef>

// Problem constants
#define BATCH   16
#define CIN     256
#define HH      64
#define WW      64
#define HW      4096
#define OC_QKV  768
#define HEADS   64
#define ATT_CH  512
#define OC_OUT  256
#define K_PROJ  512

// ---------------------------------------------------------------------------
// Scratch (pre-split hi/lo tf32 operand copies live in global)
// ---------------------------------------------------------------------------
__device__ float g_qkv [(size_t)BATCH * OC_QKV * HW];    // [b][ch][n]
__device__ float g_agg [(size_t)BATCH * OC_QKV * HW];    // [b][ch][n]
__device__ float g_kv  [(size_t)BATCH * HEADS * 72];
__device__ float g_atth[(size_t)BATCH * HW * ATT_CH];    // att hi [b][n][c]
__device__ float g_attl[(size_t)BATCH * HW * ATT_CH];    // att lo
__device__ float g_xth [(size_t)BATCH * HW * CIN];       // x^T hi [b][n][k]
__device__ float g_xtl [(size_t)BATCH * HW * CIN];       // x^T lo
__device__ float g_wqh [OC_QKV * CIN];
__device__ float g_wql [OC_QKV * CIN];
__device__ float g_wph [OC_OUT * K_PROJ];
__device__ float g_wpl [OC_OUT * K_PROJ];

// ---------------------------------------------------------------------------
// Helpers
// ---------------------------------------------------------------------------
__device__ __forceinline__ float tf32r(float x) {
    float r;
    asm("cvt.rna.tf32.f32 %0, %1;" : "=f"(r) : "f"(x));
    return r;
}

__device__ __forceinline__ void mma_tf32(float* d, const uint32_t* a, const uint32_t* b) {
    asm volatile(
        "mma.sync.aligned.m16n8k8.row.col.f32.tf32.tf32.f32 "
        "{%0,%1,%2,%3}, {%4,%5,%6,%7}, {%8,%9}, {%0,%1,%2,%3};"
        : "+f"(d[0]), "+f"(d[1]), "+f"(d[2]), "+f"(d[3])
        : "r"(a[0]), "r"(a[1]), "r"(a[2]), "r"(a[3]), "r"(b[0]), "r"(b[1]));
}

// ---------------------------------------------------------------------------
// Generic hi/lo tf32 splitter (for weight matrices)
// ---------------------------------------------------------------------------
__global__ __launch_bounds__(256)
void split_kernel(const float* __restrict__ in, float* __restrict__ h,
                  float* __restrict__ l, int n)
{
    const int i = blockIdx.x * 256 + threadIdx.x;
    if (i < n) {
        const float v  = in[i];
        const float hh = tf32r(v);
        h[i] = hh;
        l[i] = tf32r(v - hh);
    }
}

// ---------------------------------------------------------------------------
// tf32 tensor-core GEMM, pre-split operands (no CVT in hot loop).
//   C[z][m][n] = sum_k A[m][k]*B[z][n][k],  A*B ~= Ah*Bh + Al*Bh + Ah*Bl
// Smem layout: per row, k-groups of 8 stored as pairs in order
//   [ (k0 h,l)(k4 h,l)(k1 h,l)(k5 h,l)(k2 h,l)(k6 h,l)(k3 h,l)(k7 h,l) ]
// so thread tig fetches its whole fragment (h_t, l_t, h_{t+4}, l_{t+4})
// with a single LDS.128. Row pitch TP=80 floats => stride 320B = 64 mod 128
// => conflict-free per 8-lane phase.
// Block tile 128x128, K-chunk 32, 8 warps each 32(M) x 64(N).
// ---------------------------------------------------------------------------
#define TP 80
#define GEMM_SMEM (2 * 128 * TP * 4)

__global__ __launch_bounds__(256, 2)
void gemm_split(const float* __restrict__ Ah, const float* __restrict__ Al,
                const float* __restrict__ Bh, const float* __restrict__ Bl,
                float* __restrict__ C, int M, int K,
                const float* __restrict__ gamma, const float* __restrict__ beta,
                const float* __restrict__ mean,  const float* __restrict__ var)
{
    extern __shared__ float sm[];
    float* As = sm;                // [128][TP]
    float* Bs = sm + 128 * TP;     // [128][TP]

    const int tid  = threadIdx.x;
    const int wid  = tid >> 5;
    const int lane = tid & 31;
    const int g    = lane >> 2;      // 0..7
    const int tig  = lane & 3;       // 0..3

    const int n0 = blockIdx.x * 128;
    const int m0 = blockIdx.y * 128;
    const int z  = blockIdx.z;

    const int wm = (wid & 3) * 32;
    const int wn = (wid >> 2) * 64;

    const float* Bhb = Bh + (size_t)z * HW * K;
    const float* Blb = Bl + (size_t)z * HW * K;
    float*       Cb  = C  + (size_t)z * M * HW;

    float acc[2][8][4];
    #pragma unroll
    for (int mt = 0; mt < 2; mt++)
        #pragma unroll
        for (int nt = 0; nt < 8; nt++)
            #pragma unroll
            for (int j = 0; j < 4; j++) acc[mt][nt][j] = 0.f;

    // fill indexing: thread handles rows fr, fr+32, fr+64, fr+96; k cols fc..fc+3
    const int fr  = tid >> 3;
    const int fc  = (tid & 7) * 4;
    const int grp = fc >> 3;            // k-group of 8 (0..3)
    const int odd = (fc >> 2) & 1;      // low half (k%8<4) -> 0, high -> 1
    const int dof = grp * 16 + odd * 2; // float offset of first pair in row

    const int nchunks = K >> 5;
    for (int c = 0; c < nchunks; c++) {
        const int k0 = c << 5;
        #pragma unroll
        for (int it = 0; it < 4; it++) {
            const int r = fr + it * 32;
            const size_t aoff = (size_t)(m0 + r) * K + k0 + fc;
            float4 h4 = *(const float4*)(Ah + aoff);
            float4 l4 = *(const float4*)(Al + aoff);
            float* dA = As + r * TP + dof;
            *(float2*)(dA + 0)  = make_float2(h4.x, l4.x);
            *(float2*)(dA + 4)  = make_float2(h4.y, l4.y);
            *(float2*)(dA + 8)  = make_float2(h4.z, l4.z);
            *(float2*)(dA + 12) = make_float2(h4.w, l4.w);

            const size_t boff = (size_t)(n0 + r) * K + k0 + fc;
            h4 = *(const float4*)(Bhb + boff);
            l4 = *(const float4*)(Blb + boff);
            float* dB = Bs + r * TP + dof;
            *(float2*)(dB + 0)  = make_float2(h4.x, l4.x);
            *(float2*)(dB + 4)  = make_float2(h4.y, l4.y);
            *(float2*)(dB + 8)  = make_float2(h4.z, l4.z);
            *(float2*)(dB + 12) = make_float2(h4.w, l4.w);
        }
        __syncthreads();

        #pragma unroll
        for (int ks = 0; ks < 4; ks++) {
            const int col = ks * 16 + tig * 4;   // float offset of this thread's frag
            uint32_t bh[8][2], bl[8][2];
            #pragma unroll
            for (int nt = 0; nt < 8; nt++) {
                const int n = wn + nt * 8 + g;
                float4 rb = *(const float4*)(Bs + n * TP + col);
                bh[nt][0] = __float_as_uint(rb.x);
                bl[nt][0] = __float_as_uint(rb.y);
                bh[nt][1] = __float_as_uint(rb.z);
                bl[nt][1] = __float_as_uint(rb.w);
            }
            #pragma unroll
            for (int mt = 0; mt < 2; mt++) {
                const int mr = wm + mt * 16;
                float4 r1 = *(const float4*)(As + (mr + g    ) * TP + col);
                float4 r2 = *(const float4*)(As + (mr + 8 + g) * TP + col);
                uint32_t ahi[4] = { __float_as_uint(r1.x), __float_as_uint(r2.x),
                                    __float_as_uint(r1.z), __float_as_uint(r2.z) };
                uint32_t alo[4] = { __float_as_uint(r1.y), __float_as_uint(r2.y),
                                    __float_as_uint(r1.w), __float_as_uint(r2.w) };
                #pragma unroll
                for (int nt = 0; nt < 8; nt++) {
                    mma_tf32(acc[mt][nt], alo, bh[nt]);   // Al*Bh
                    mma_tf32(acc[mt][nt], ahi, bl[nt]);   // Ah*Bl
                    mma_tf32(acc[mt][nt], ahi, bh[nt]);   // Ah*Bh
                }
            }
        }
        __syncthreads();
    }

    // --- epilogue ---
    #pragma unroll
    for (int mt = 0; mt < 2; mt++) {
        const int mA = m0 + wm + mt * 16 + g;
        const int mB = mA + 8;
        float sA = 1.f, hA = 0.f, sB = 1.f, hB = 0.f;
        if (gamma) {
            float invA = gamma[mA] * rsqrtf(var[mA] + 1e-5f);
            float invB = gamma[mB] * rsqrtf(var[mB] + 1e-5f);
            sA = invA; hA = beta[mA] - mean[mA] * invA;
            sB = invB; hB = beta[mB] - mean[mB] * invB;
        }
        float* rowA = Cb + (size_t)mA * HW + n0 + wn + 2 * tig;
        float* rowB = Cb + (size_t)mB * HW + n0 + wn + 2 * tig;
        #pragma unroll
        for (int nt = 0; nt < 8; nt++) {
            float2 oA, oB;
            oA.x = acc[mt][nt][0] * sA + hA;
            oA.y = acc[mt][nt][1] * sA + hA;
            oB.x = acc[mt][nt][2] * sB + hB;
            oB.y = acc[mt][nt][3] * sB + hB;
            *(float2*)(rowA + nt * 8) = oA;
            *(float2*)(rowB + nt * 8) = oB;
        }
    }
}

// ---------------------------------------------------------------------------
// Transpose x: [b][k=256][n=4096] -> xt_h/xt_l [b][n][k] (pre-split)
// ---------------------------------------------------------------------------
__global__ __launch_bounds__(256)
void transpose_kernel(const float* __restrict__ in,
                      float* __restrict__ oh, float* __restrict__ ol)
{
    __shared__ float t[32][33];
    const int b  = blockIdx.z;
    const int n0 = blockIdx.x * 32;
    const int k0 = blockIdx.y * 32;
    const int tx = threadIdx.x & 31;
    const int ty = threadIdx.x >> 5;

    const float* ib = in + (size_t)b * CIN * HW;
    float* ohb = oh + (size_t)b * HW * CIN;
    float* olb = ol + (size_t)b * HW * CIN;

    #pragma unroll
    for (int i = 0; i < 4; i++) {
        const int k = k0 + ty + i * 8;
        t[ty + i * 8][tx] = ib[(size_t)k * HW + n0 + tx];
    }
    __syncthreads();
    #pragma unroll
    for (int i = 0; i < 4; i++) {
        const int n = n0 + ty + i * 8;
        const float v = t[tx][ty + i * 8];
        const float h = tf32r(v);
        ohb[(size_t)n * CIN + k0 + tx] = h;
        olb[(size_t)n * CIN + k0 + tx] = tf32r(v - h);
    }
}

// ---------------------------------------------------------------------------
// Fused depthwise 3x3 + grouped 1x1
// ---------------------------------------------------------------------------
__global__ __launch_bounds__(256)
void dwpw_kernel(const float* __restrict__ qkv,
                 const float* __restrict__ wdw,
                 const float* __restrict__ wpw,
                 float* __restrict__ agg)
{
    const int strip = blockIdx.x;
    const int gg    = blockIdx.y;
    const int b     = blockIdx.z;
    const int r0    = strip * 16;

    __shared__ float s_in[8][18][68];
    __shared__ float s_wdw[8][9];
    __shared__ float s_wpw[8][8];

    const int tid = threadIdx.x;
    const float* base = qkv + ((size_t)b * OC_QKV + gg * 8) * HW;

    for (int idx = tid; idx < 8 * 18 * 16; idx += 256) {
        const int seg = idx & 15;
        const int row = idx >> 4;
        const int rr  = row % 18;
        const int ch  = row / 18;
        const int y   = r0 + rr - 1;
        float4 v = make_float4(0.f, 0.f, 0.f, 0.f);
        if (y >= 0 && y < HH)
            v = *(const float4*)(base + (size_t)ch * HW + y * WW + seg * 4);
        float* d = &s_in[ch][rr][1 + seg * 4];
        d[0] = v.x; d[1] = v.y; d[2] = v.z; d[3] = v.w;
        if (seg == 0)  s_in[ch][rr][0]  = 0.f;
        if (seg == 15) s_in[ch][rr][65] = 0.f;
    }
    if (tid < 72)
        s_wdw[tid / 9][tid % 9] = wdw[(size_t)(gg * 8 + tid / 9) * 9 + tid % 9];
    if (tid >= 128 && tid < 192) {
        int t = tid - 128;
        s_wpw[t >> 3][t & 7] = wpw[(size_t)(gg * 8 + (t >> 3)) * 8 + (t & 7)];
    }
    __syncthreads();

    float* obase = agg + ((size_t)b * OC_QKV + gg * 8) * HW + r0 * WW;
    for (int p = tid; p < 16 * WW; p += 256) {
        const int py = p >> 6;
        const int px = p & 63;
        float dwv[8];
        #pragma unroll
        for (int ic = 0; ic < 8; ic++) {
            float s = 0.f;
            #pragma unroll
            for (int ky = 0; ky < 3; ky++)
                #pragma unroll
                for (int kx = 0; kx < 3; kx++)
                    s += s_in[ic][py + ky][px + kx] * s_wdw[ic][ky * 3 + kx];
            dwv[ic] = s;
        }
        #pragma unroll
        for (int oc = 0; oc < 8; oc++) {
            float s = 0.f;
            #pragma unroll
            for (int ic = 0; ic < 8; ic++) s += s_wpw[oc][ic] * dwv[ic];
            obase[(size_t)oc * HW + p] = s;
        }
    }
}

// ---------------------------------------------------------------------------
// kv reduction
// ---------------------------------------------------------------------------
__global__ __launch_bounds__(256)
void kv_kernel(const float* __restrict__ qkv, const float* __restrict__ agg,
               float* __restrict__ kvout)
{
    const int h = blockIdx.x;
    const int b = blockIdx.y;
    const float* src = (h < 32) ? qkv : agg;
    const int ch0 = (h & 31) * 24;
    const float* base = src + ((size_t)b * OC_QKV + ch0) * HW;

    float acc[8][9];
    #pragma unroll
    for (int d = 0; d < 8; d++)
        #pragma unroll
        for (int e = 0; e < 9; e++) acc[d][e] = 0.f;

    for (int n = threadIdx.x; n < HW; n += 256) {
        float kk[8], vv[8];
        #pragma unroll
        for (int d = 0; d < 8; d++)
            kk[d] = fmaxf(base[(size_t)(8 + d) * HW + n], 0.f);
        #pragma unroll
        for (int e = 0; e < 8; e++)
            vv[e] = base[(size_t)(16 + e) * HW + n];
        #pragma unroll
        for (int d = 0; d < 8; d++) {
            #pragma unroll
            for (int e = 0; e < 8; e++) acc[d][e] += kk[d] * vv[e];
            acc[d][8] += kk[d];
        }
    }

    __shared__ float sred[8][72];
    const int lane = threadIdx.x & 31;
    const int warp = threadIdx.x >> 5;
    #pragma unroll
    for (int d = 0; d < 8; d++)
        #pragma unroll
        for (int e = 0; e < 9; e++) {
            float v = acc[d][e];
            #pragma unroll
            for (int o = 16; o > 0; o >>= 1)
                v += __shfl_down_sync(0xffffffffu, v, o);
            if (lane == 0) sred[warp][d * 9 + e] = v;
        }
    __syncthreads();
    if (threadIdx.x < 72) {
        float s = 0.f;
        #pragma unroll
        for (int w = 0; w < 8; w++) s += sred[w][threadIdx.x];
        kvout[((size_t)b * HEADS + h) * 72 + threadIdx.x] = s;
    }
}

// ---------------------------------------------------------------------------
// attention apply -> writes pre-split TRANSPOSED att (hi/lo) [b][n][c]
// ---------------------------------------------------------------------------
__global__ __launch_bounds__(256)
void apply_kernel(const float* __restrict__ qkv, const float* __restrict__ agg,
                  const float* __restrict__ kvin,
                  float* __restrict__ atth, float* __restrict__ attl)
{
    const int h = blockIdx.x;
    const int b = blockIdx.y;
    const float* src = (h < 32) ? qkv : agg;
    const int ch0 = (h & 31) * 24;
    const float* qb = src + ((size_t)b * OC_QKV + ch0) * HW;

    __shared__ float s_kv[72];
    if (threadIdx.x < 72)
        s_kv[threadIdx.x] = kvin[((size_t)b * HEADS + h) * 72 + threadIdx.x];
    __syncthreads();

    float* obh = atth + (size_t)b * HW * ATT_CH + h * 8;
    float* obl = attl + (size_t)b * HW * ATT_CH + h * 8;
    for (int n = threadIdx.x; n < HW; n += 256) {
        float q[8];
        #pragma unroll
        for (int d = 0; d < 8; d++)
            q[d] = fmaxf(qb[(size_t)d * HW + n], 0.f);
        float num[9];
        #pragma unroll
        for (int e = 0; e < 9; e++) {
            float s = 0.f;
            #pragma unroll
            for (int d = 0; d < 8; d++) s += q[d] * s_kv[d * 9 + e];
            num[e] = s;
        }
        const float r = 1.0f / (num[8] + 1e-15f);
        float4 oh0, oh1, ol0, ol1;
        float vv, hh;
        vv = num[0] * r; hh = tf32r(vv); oh0.x = hh; ol0.x = tf32r(vv - hh);
        vv = num[1] * r; hh = tf32r(vv); oh0.y = hh; ol0.y = tf32r(vv - hh);
        vv = num[2] * r; hh = tf32r(vv); oh0.z = hh; ol0.z = tf32r(vv - hh);
        vv = num[3] * r; hh = tf32r(vv); oh0.w = hh; ol0.w = tf32r(vv - hh);
        vv = num[4] * r; hh = tf32r(vv); oh1.x = hh; ol1.x = tf32r(vv - hh);
        vv = num[5] * r; hh = tf32r(vv); oh1.y = hh; ol1.y = tf32r(vv - hh);
        vv = num[6] * r; hh = tf32r(vv); oh1.z = hh; ol1.z = tf32r(vv - hh);
        vv = num[7] * r; hh = tf32r(vv); oh1.w = hh; ol1.w = tf32r(vv - hh);
        float* dh = obh + (size_t)n * ATT_CH;
        float* dl = obl + (size_t)n * ATT_CH;
        *(float4*)(dh)     = oh0;
        *(float4*)(dh + 4) = oh1;
        *(float4*)(dl)     = ol0;
        *(float4*)(dl + 4) = ol1;
    }
}

// ---------------------------------------------------------------------------
// Launch
// ---------------------------------------------------------------------------
extern "C" void kernel_launch(void* const* d_in, const int* in_sizes, int n_in,
                              void* d_out, int out_size)
{
    const float* x      = (const float*)d_in[0];
    const float* w_qkv  = (const float*)d_in[1];
    const float* w_dw   = (const float*)d_in[2];
    const float* w_pw   = (const float*)d_in[3];
    const float* w_proj = (const float*)d_in[4];
    const float* gamma  = (const float*)d_in[5];
    const float* beta   = (const float*)d_in[6];
    const float* mean   = (const float*)d_in[7];
    const float* var    = (const float*)d_in[8];
    float* out = (float*)d_out;

    float *qkv_p, *agg_p, *kv_p, *atth_p, *attl_p, *xth_p, *xtl_p;
    float *wqh_p, *wql_p, *wph_p, *wpl_p;
    cudaGetSymbolAddress((void**)&qkv_p,  g_qkv);
    cudaGetSymbolAddress((void**)&agg_p,  g_agg);
    cudaGetSymbolAddress((void**)&kv_p,   g_kv);
    cudaGetSymbolAddress((void**)&atth_p, g_atth);
    cudaGetSymbolAddress((void**)&attl_p, g_attl);
    cudaGetSymbolAddress((void**)&xth_p,  g_xth);
    cudaGetSymbolAddress((void**)&xtl_p,  g_xtl);
    cudaGetSymbolAddress((void**)&wqh_p,  g_wqh);
    cudaGetSymbolAddress((void**)&wql_p,  g_wql);
    cudaGetSymbolAddress((void**)&wph_p,  g_wph);
    cudaGetSymbolAddress((void**)&wpl_p,  g_wpl);

    cudaFuncSetAttribute(gemm_split, cudaFuncAttributeMaxDynamicSharedMemorySize, GEMM_SMEM);

    // 0) split weights + transpose/split x
    split_kernel<<<(OC_QKV * CIN + 255) / 256, 256>>>(w_qkv, wqh_p, wql_p, OC_QKV * CIN);
    split_kernel<<<(OC_OUT * K_PROJ + 255) / 256, 256>>>(w_proj, wph_p, wpl_p, OC_OUT * K_PROJ);
    {
        dim3 grid(HW / 32, CIN / 32, BATCH);
        transpose_kernel<<<grid, 256>>>(x, xth_p, xtl_p);
    }
    // 1) qkv = W_qkv * x : M=768, K=256
    {
        dim3 grid(HW / 128, OC_QKV / 128, BATCH);
        gemm_split<<<grid, 256, GEMM_SMEM>>>(wqh_p, wql_p, xth_p, xtl_p, qkv_p,
                                             OC_QKV, CIN,
                                             nullptr, nullptr, nullptr, nullptr);
    }
    // 2) depthwise + grouped pointwise
    {
        dim3 grid(4, 96, BATCH);
        dwpw_kernel<<<grid, 256>>>(qkv_p, w_dw, w_pw, agg_p);
    }
    // 3) kv reduction
    {
        dim3 grid(HEADS, BATCH);
        kv_kernel<<<grid, 256>>>(qkv_p, agg_p, kv_p);
    }
    // 4) attention apply (writes pre-split transposed att)
    {
        dim3 grid(HEADS, BATCH);
        apply_kernel<<<grid, 256>>>(qkv_p, agg_p, kv_p, atth_p, attl_p);
    }
    // 5) y = W_proj * att + BN : M=256, K=512
    {
        dim3 grid(HW / 128, OC_OUT / 128, BATCH);
        gemm_split<<<grid, 256, GEMM_SMEM>>>(wph_p, wpl_p, atth_p, attl_p, out,
                                             OC_OUT, K_PROJ,
                                             gamma, beta, mean, var);
    }
}